// round 16
// baseline (speedup 1.0000x reference)
#include <cuda_runtime.h>
#include <math.h>
#include <stdint.h>

#define B    512
#define NP   200
#define EPG  2000
#define E_TOT (B*EPG)
#define HID  128
#define EMB  9
#define K1   160
#define K2   128
#define K3   103

#define NT   832           // threads (26 warps)
#define NW   26            // warps
#define INV_E 0xFFu
#define XSTR 132           // xs/ms row stride (floats)

// ---------------- async copy helpers -----------------------------------------
__device__ __forceinline__ void cp_async16(void* smem_dst, const void* gsrc) {
    uint32_t s = (uint32_t)__cvta_generic_to_shared(smem_dst);
    asm volatile("cp.async.ca.shared.global [%0], [%1], 16;\n" :: "r"(s), "l"(gsrc));
}
__device__ __forceinline__ void cp_commit() {
    asm volatile("cp.async.commit_group;\n" ::: "memory");
}
template<int N>
__device__ __forceinline__ void cp_wait() {
    asm volatile("cp.async.wait_group %0;\n" :: "n"(N) : "memory");
}

// ---------------- tf32 mma + ldmatrix primitives ------------------------------
__device__ __forceinline__ void mma_tf32(float c[4], uint32_t a0, uint32_t a1,
                                         uint32_t a2, uint32_t a3,
                                         uint32_t b0, uint32_t b1) {
    asm volatile(
        "mma.sync.aligned.m16n8k8.row.col.f32.tf32.tf32.f32 "
        "{%0,%1,%2,%3}, {%4,%5,%6,%7}, {%8,%9}, {%0,%1,%2,%3};"
        : "+f"(c[0]), "+f"(c[1]), "+f"(c[2]), "+f"(c[3])
        : "r"(a0), "r"(a1), "r"(a2), "r"(a3), "r"(b0), "r"(b1));
}
__device__ __forceinline__ void ldsm4(uint32_t r[4], uint32_t addr) {
    asm volatile("ldmatrix.sync.aligned.m8n8.x4.shared.b16 {%0,%1,%2,%3}, [%4];"
        : "=r"(r[0]), "=r"(r[1]), "=r"(r[2]), "=r"(r[3]) : "r"(addr));
}
__device__ __forceinline__ uint32_t smem_u32(const void* p) {
    return (uint32_t)__cvta_generic_to_shared(p);
}

// ---------------- mega kernel smem -------------------------------------------
struct MegaSm {
    float xs[160][XSTR];     // pooled features (current space)
    float ms[160][XSTR];     // neighbor means (current space)
    union {
        struct {             // conv1 phase
            float As1[208][28];   // [mean(9) | x(9) | pad] per node
            float W1s[128][28];   // [w1n | w1r | pad]
        } c1;
        float wst2[2][128][36];  // level-GEMM W k-chunk double buffer
    } u;
    float s[208];            // scores (n is always a multiple of 4)
    float sdp[4][208];       // deterministic 4-part score dot (conv1 uses 2)
    float bb[128];
    float ps[128];
    float harr[256];         // readout accumulator x1+x2+x3
    float pmax[6][128];
    float psum[6][128];
    float h1[128];
    float h2[64];
    float rns[3];
    int   hist[224];
    int   off[225];          // ORIGINAL-space CSR offsets (built once)
    int   cur[224];
    int   wsum[8];
    short newloc[208];
    short kept[160];
    short o2c[208];          // orig -> current (composed across topks), -1 dead
    short c2o[2][160];       // current -> orig per level (0: after topk1)
    unsigned char esrc[EPG];
    unsigned char edst[EPG];
    unsigned char eord[EPG]; // srcs sorted by ORIGINAL dst (built once)
};

// parallel exclusive scan of hist[0..n) -> off/cur, off[n]=total
__device__ __forceinline__ void excl_scan(MegaSm* S, int n) {
    int tid = threadIdx.x, lane = tid & 31, w = tid >> 5;
    int npad = (n + 31) & ~31;
    if (tid < npad) {
        int h0 = S->hist[tid];
        int x = h0;
#pragma unroll
        for (int o = 1; o < 32; o <<= 1) {
            int y = __shfl_up_sync(0xffffffffu, x, o);
            if (lane >= o) x += y;
        }
        if (lane == 31) S->wsum[w] = x;
        S->off[tid] = x - h0;
    }
    __syncthreads();
    if (tid == 0) {
        int a = 0, nw = npad >> 5;
        for (int i = 0; i < nw; i++) { int t = S->wsum[i]; S->wsum[i] = a; a += t; }
        S->off[n] = a;
    }
    __syncthreads();
    if (tid < n) {
        int o = S->off[tid] + S->wsum[w];
        S->off[tid] = o;
        S->cur[tid] = o;
    }
    __syncthreads();
}

// one-time counting sort of edges by ORIGINAL dst into eord
__device__ __forceinline__ void edge_sort_once(MegaSm* S) {
    int tid = threadIdx.x;
    for (int i = tid; i < 224; i += NT) S->hist[i] = 0;
    __syncthreads();
    for (int e = tid; e < EPG; e += NT)
        atomicAdd(&S->hist[S->edst[e]], 1);
    __syncthreads();
    excl_scan(S, NP);
    for (int e = tid; e < EPG; e += NT) {
        int p = atomicAdd(&S->cur[S->edst[e]], 1);
        S->eord[p] = S->esrc[e];
    }
    __syncthreads();
}

// 128-dim neighbor mean at levels 2/3: single tight chain (R13 form).
__device__ __forceinline__ void level_agg2(MegaSm* S, int n, const short* c2o) {
    __syncthreads();     // o2c/c2o/xs visibility
    int tid = threadIdx.x, w = tid >> 5, lane = tid & 31;
    for (int v = w; v < n; v += NW) {
        int ov = c2o[v];
        int e0 = S->off[ov], e1 = S->off[ov + 1];
        float4 a = make_float4(0.f, 0.f, 0.f, 0.f);
        int cnt = 0;
        for (int e = e0; e < e1; e++) {
            int cs = S->o2c[S->eord[e]];
            if (cs >= 0) {
                float4 p = *(const float4*)&S->xs[cs][4*lane];
                a.x += p.x; a.y += p.y; a.z += p.z; a.w += p.w;
                cnt++;
            }
        }
        float inv = (cnt > 0) ? 1.0f / (float)cnt : 0.0f;
        *(float4*)&S->ms[v][4*lane] =
            make_float4(a.x * inv, a.y * inv, a.z * inv, a.w * inv);
    }
    __syncthreads();
}

// 3-way split rank with float4 inner loads; hist pre-zeroed by caller.
// Threads with part*chunk >= n contribute nothing (empty range).
__device__ __forceinline__ void level_rank(MegaSm* S, int n, int k) {
    int tid = threadIdx.x;
    int v = tid & 255;
    int part = tid >> 8;                 // 0..3 (832 threads)
    if (v < n) {
        int chunk = (((n + 2) / 3) + 3) & ~3;
        int u0 = part * chunk;
        int u1 = min(n, u0 + chunk);
        float sv = S->s[v];
        int r = 0;
        int u = u0;
        for (; u + 4 <= u1; u += 4) {
            float4 s4 = *(const float4*)&S->s[u];
            r += (s4.x > sv) || (s4.x == sv && (u + 0) < v);
            r += (s4.y > sv) || (s4.y == sv && (u + 1) < v);
            r += (s4.z > sv) || (s4.z == sv && (u + 2) < v);
            r += (s4.w > sv) || (s4.w == sv && (u + 3) < v);
        }
        for (; u < u1; u++) {
            float su = S->s[u];
            r += (su > sv) || (su == sv && u < v);
        }
        if (r) atomicAdd(&S->hist[v], r);
    }
    __syncthreads();
    for (int v2 = tid; v2 < n; v2 += NT) {
        int r = S->hist[v2];
        S->newloc[v2] = (r < k) ? (short)r : (short)-1;
        if (r < k) S->kept[r] = (short)v2;
    }
    __syncthreads();
}

// pool xs rows [0,k) into harr (6 row-slices on first 768 threads).
// No trailing sync (audited).
__device__ __forceinline__ void pool_xs(MegaSm* S, int k) {
    int tid = threadIdx.x;
    if (tid < 768) {
        int d = tid & 127, sl = tid >> 7;    // 0..5
        float mx = -INFINITY, sm = 0.0f;
        for (int r = sl; r < k; r += 6) {
            float v = S->xs[r][d];
            mx = fmaxf(mx, v);
            sm += v;
        }
        S->pmax[sl][d] = mx;
        S->psum[sl][d] = sm;
    }
    __syncthreads();
    if (tid < 128) {
        float m = S->pmax[0][tid];
        float t = S->psum[0][tid];
#pragma unroll
        for (int i = 1; i < 6; i++) {
            m = fmaxf(m, S->pmax[i][tid]);
            t += S->psum[i][tid];
        }
        S->harr[tid]       += m;
        S->harr[128 + tid] += t / (float)k;
    }
}

// stage one 32-k chunk of the level weights into wst2[buf]
__device__ __forceinline__ void stage_chunk(
        MegaSm* S, int buf, const float* __restrict__ Wn,
        const float* __restrict__ Wr, int ci) {
    const float* Wg = (ci < 4) ? Wn : Wr;
    int kg = (ci * 32) & 127;
    int tid = threadIdx.x;
    for (int idx = tid; idx < 1024; idx += NT) {
        int r = idx >> 3, q = idx & 7;
        cp_async16(&S->u.wst2[buf][r][q * 4], &Wg[r * 128 + kg + q * 4]);
    }
    cp_commit();
}

// level GEMM, single sync per k-chunk, LDSM fragment loads.
// Fused score+topk+scatter+pool.
__device__ __forceinline__ void level_gemm_topk(
        MegaSm* S, int n, int k, float rn,
        const float* __restrict__ Wn, const float* __restrict__ Wr) {
    int tid = threadIdx.x, lane = tid & 31, w = tid >> 5;
    int rg = w >> 2, cf = w & 3;
    bool active = (rg < (n >> 5));

    // ldmatrix lane roles
    int t8    = lane >> 3;                       // tile index 0..3
    int lane7 = lane & 7;
    int aRow  = rg * 32 + (t8 & 1) * 8 + lane7;  // A: tiles 0/2 rows, 1/3 rows+8
    int aColO = (t8 >> 1) * 4;                   // A: tiles 2,3 at col+4
    int bRow  = cf * 32 + (t8 >> 1) * 8 + lane7; // B: tile pair rows
    int bColO = (t8 & 1) * 4;                    // B: tiles 1,3 at col+4

    float acc[2][4][4];
#pragma unroll
    for (int mt = 0; mt < 2; mt++)
#pragma unroll
        for (int nt = 0; nt < 4; nt++)
#pragma unroll
            for (int i = 0; i < 4; i++) acc[mt][nt][i] = 0.0f;

#pragma unroll 1
    for (int ci = 0; ci < 8; ci++) {
        cp_wait<0>();
        __syncthreads();   // chunk ci visible; all warps done with buf (ci+1)&1
        if (ci < 7) stage_chunk(S, (ci + 1) & 1, Wn, Wr, ci + 1);

        int nb = ci & 1;
        if (active) {
            int kc = ci * 32;
            const float (*A)[XSTR] = (kc < 128) ? S->ms : S->xs;
            int kg = kc & 127;
            uint32_t aA = smem_u32(&A[aRow][kg + aColO]);
            uint32_t aB = smem_u32(&S->u.wst2[nb][bRow][bColO]);
#pragma unroll
            for (int ks = 0; ks < 32; ks += 8) {
                uint32_t am0[4], am1[4], bp0[4], bp1[4];
                ldsm4(am0, aA + ks * 4);
                ldsm4(am1, aA + 16 * XSTR * 4 + ks * 4);
                ldsm4(bp0, aB + ks * 4);
                ldsm4(bp1, aB + 16 * 36 * 4 + ks * 4);
                mma_tf32(acc[0][0], am0[0], am0[1], am0[2], am0[3], bp0[0], bp0[1]);
                mma_tf32(acc[0][1], am0[0], am0[1], am0[2], am0[3], bp0[2], bp0[3]);
                mma_tf32(acc[0][2], am0[0], am0[1], am0[2], am0[3], bp1[0], bp1[1]);
                mma_tf32(acc[0][3], am0[0], am0[1], am0[2], am0[3], bp1[2], bp1[3]);
                mma_tf32(acc[1][0], am1[0], am1[1], am1[2], am1[3], bp0[0], bp0[1]);
                mma_tf32(acc[1][1], am1[0], am1[1], am1[2], am1[3], bp0[2], bp0[3]);
                mma_tf32(acc[1][2], am1[0], am1[1], am1[2], am1[3], bp1[0], bp1[1]);
                mma_tf32(acc[1][3], am1[0], am1[1], am1[2], am1[3], bp1[2], bp1[3]);
            }
        }
    }

    if (active) {
#pragma unroll
        for (int mt = 0; mt < 2; mt++) {
            int r = rg * 32 + mt * 16 + (lane >> 2);
            float pd0 = 0.0f, pd1 = 0.0f;
#pragma unroll
            for (int nt = 0; nt < 4; nt++) {
                int col = cf * 32 + nt * 8 + 2 * (lane & 3);
                float v00 = fmaxf(acc[mt][nt][0] + S->bb[col],     0.0f);
                float v01 = fmaxf(acc[mt][nt][1] + S->bb[col + 1], 0.0f);
                float v10 = fmaxf(acc[mt][nt][2] + S->bb[col],     0.0f);
                float v11 = fmaxf(acc[mt][nt][3] + S->bb[col + 1], 0.0f);
                acc[mt][nt][0] = v00; acc[mt][nt][1] = v01;
                acc[mt][nt][2] = v10; acc[mt][nt][3] = v11;
                pd0 += v00 * S->ps[col] + v01 * S->ps[col + 1];
                pd1 += v10 * S->ps[col] + v11 * S->ps[col + 1];
            }
            pd0 += __shfl_xor_sync(0xffffffffu, pd0, 1);
            pd0 += __shfl_xor_sync(0xffffffffu, pd0, 2);
            pd1 += __shfl_xor_sync(0xffffffffu, pd1, 1);
            pd1 += __shfl_xor_sync(0xffffffffu, pd1, 2);
            if ((lane & 3) == 0) { S->sdp[cf][r] = pd0; S->sdp[cf][r + 8] = pd1; }
        }
    }
    __syncthreads();

    // score write + rank-hist zeroing in one synced phase
    for (int v = tid; v < n; v += NT) {
        S->s[v] = tanhf(((S->sdp[0][v] + S->sdp[1][v]) +
                         (S->sdp[2][v] + S->sdp[3][v])) * rn);
        S->hist[v] = 0;
    }
    __syncthreads();

    level_rank(S, n, k);

    if (active) {
#pragma unroll
        for (int mt = 0; mt < 2; mt++) {
            int r = rg * 32 + mt * 16 + (lane >> 2);
            int nl0 = S->newloc[r], nl1 = S->newloc[r + 8];
            float s0 = S->s[r], s1 = S->s[r + 8];
#pragma unroll
            for (int nt = 0; nt < 4; nt++) {
                int col = cf * 32 + nt * 8 + 2 * (lane & 3);
                if (nl0 >= 0)
                    *(float2*)&S->xs[nl0][col] =
                        make_float2(acc[mt][nt][0] * s0, acc[mt][nt][1] * s0);
                if (nl1 >= 0)
                    *(float2*)&S->xs[nl1][col] =
                        make_float2(acc[mt][nt][2] * s1, acc[mt][nt][3] * s1);
            }
        }
    }
    __syncthreads();

    pool_xs(S, k);
}

// ---------------- the single fused kernel ------------------------------------
__global__ __launch_bounds__(NT, 1) void mega_kernel(
        const int* __restrict__ node_ids,
        const int* __restrict__ edge_index,
        const float* __restrict__ emb,
        const float* __restrict__ w1n, const float* __restrict__ w1r,
        const float* __restrict__ b1,  const float* __restrict__ p1,
        const float* __restrict__ w2n, const float* __restrict__ w2r,
        const float* __restrict__ b2,  const float* __restrict__ p2,
        const float* __restrict__ w3n, const float* __restrict__ w3r,
        const float* __restrict__ b3,  const float* __restrict__ p3,
        const float* __restrict__ lw1, const float* __restrict__ lb1,
        const float* __restrict__ lw2, const float* __restrict__ lb2,
        const float* __restrict__ lw3, const float* __restrict__ lb3,
        float* __restrict__ out) {
    extern __shared__ char raw[];
    MegaSm* S = (MegaSm*)raw;

    int b = blockIdx.x, tid = threadIdx.x;
    int w = tid >> 5, lane = tid & 31;

    // edges -> smem (uint8 original indices)
    for (int e = tid; e < EPG; e += NT) {
        S->esrc[e] = (unsigned char)(edge_index[b*EPG + e] - b*NP);
        S->edst[e] = (unsigned char)(edge_index[E_TOT + b*EPG + e] - b*NP);
    }
    // 1/||p|| for the three pool vectors
    if (w < 3) {
        const float* pv = (w == 0) ? p1 : ((w == 1) ? p2 : p3);
        float v = pv[lane]*pv[lane] + pv[lane+32]*pv[lane+32]
                + pv[lane+64]*pv[lane+64] + pv[lane+96]*pv[lane+96];
#pragma unroll
        for (int o = 16; o; o >>= 1) v += __shfl_down_sync(0xffffffffu, v, o);
        if (lane == 0) S->rns[w] = 1.0f / sqrtf(v);
    }
    if (tid < 256) S->harr[tid] = 0.0f;
    if (tid < 128) { S->bb[tid] = b1[tid]; S->ps[tid] = p1[tid]; }

    // As1: zero everything; fill emb features into cols 9..17 for v<200
    for (int idx = tid; idx < 208*28; idx += NT) {
        int r = idx / 28, c = idx - r*28;
        float v = 0.0f;
        if (r < NP && c >= 9 && c < 18)
            v = emb[(size_t)node_ids[b*NP + r] * EMB + (c - 9)];
        S->u.c1.As1[r][c] = v;
    }
    // W1 stage [w1n | w1r | pad]
    for (int idx = tid; idx < 128*28; idx += NT) {
        int r = idx / 28, c = idx - r*28;
        float wv = 0.0f;
        if (c < 9)       wv = w1n[r*9 + c];
        else if (c < 18) wv = w1r[r*9 + (c - 9)];
        S->u.c1.W1s[r][c] = wv;
    }
    __syncthreads();

    // ---------- one-time edge sort + level-1 9-dim aggregation ----------
    edge_sort_once(S);
    for (int v = w; v < NP; v += NW) {
        int e0 = S->off[v], e1 = S->off[v+1];
        float inv = (e1 > e0) ? 1.0f / (float)(e1 - e0) : 0.0f;
        if (lane < EMB) {
            float a = 0.0f;
            for (int e = e0; e < e1; e++)
                a += S->u.c1.As1[S->eord[e]][9 + lane];
            S->u.c1.As1[v][lane] = a * inv;
        }
    }
    __syncthreads();

    // ldmatrix lane roles (shared by conv1 passes)
    int t8    = lane >> 3;
    int lane7 = lane & 7;
    int aRowO = (t8 & 1) * 8 + lane7;
    int aColO = (t8 >> 1) * 4;
    int bRowO = (t8 >> 1) * 8 + lane7;
    int bColO = (t8 & 1) * 4;

    // ---------- conv1 pass 1: score dot only (26 tasks = 26 warps, LDSM) -----
    if (w < 26) {
        int rg = w >> 1, hf = w & 1;
        float acc[8][4];
#pragma unroll
        for (int nt = 0; nt < 8; nt++)
#pragma unroll
            for (int i = 0; i < 4; i++) acc[nt][i] = 0.0f;
        uint32_t aA = smem_u32(&S->u.c1.As1[rg * 16 + aRowO][aColO]);
        uint32_t aB = smem_u32(&S->u.c1.W1s[hf * 64 + bRowO][bColO]);
#pragma unroll
        for (int ks = 0; ks < 24; ks += 8) {
            uint32_t am[4];
            ldsm4(am, aA + ks * 4);
#pragma unroll
            for (int p = 0; p < 4; p++) {
                uint32_t bp[4];
                ldsm4(bp, aB + p * 16 * 28 * 4 + ks * 4);
                mma_tf32(acc[2*p],   am[0], am[1], am[2], am[3], bp[0], bp[1]);
                mma_tf32(acc[2*p+1], am[0], am[1], am[2], am[3], bp[2], bp[3]);
            }
        }
        int r = rg * 16 + (lane >> 2);
        float pd0 = 0.0f, pd1 = 0.0f;
#pragma unroll
        for (int nt = 0; nt < 8; nt++) {
            int col = hf * 64 + nt * 8 + 2 * (lane & 3);
            pd0 += fmaxf(acc[nt][0] + S->bb[col],     0.0f) * S->ps[col]
                 + fmaxf(acc[nt][1] + S->bb[col + 1], 0.0f) * S->ps[col + 1];
            pd1 += fmaxf(acc[nt][2] + S->bb[col],     0.0f) * S->ps[col]
                 + fmaxf(acc[nt][3] + S->bb[col + 1], 0.0f) * S->ps[col + 1];
        }
        pd0 += __shfl_xor_sync(0xffffffffu, pd0, 1);
        pd0 += __shfl_xor_sync(0xffffffffu, pd0, 2);
        pd1 += __shfl_xor_sync(0xffffffffu, pd1, 1);
        pd1 += __shfl_xor_sync(0xffffffffu, pd1, 2);
        if ((lane & 3) == 0) { S->sdp[hf][r] = pd0; S->sdp[hf][r + 8] = pd1; }
    }
    __syncthreads();

    for (int v = tid; v < NP; v += NT) {
        S->s[v] = tanhf((S->sdp[0][v] + S->sdp[1][v]) * S->rns[0]);
        S->hist[v] = 0;
    }
    __syncthreads();

    level_rank(S, NP, K1);

    // init composed maps (level-1 current == original space)
    for (int ov = tid; ov < NP; ov += NT) S->o2c[ov] = S->newloc[ov];
    for (int r = tid; r < K1; r += NT)   S->c2o[0][r] = S->kept[r];

    // ---------- conv1 pass 2: kept-row recompute via gathered-row LDSM -------
    if (w < 20) {
        int rg = w >> 1, hf = w & 1;
        int r0 = rg * 16 + (lane >> 2);
        int k0 = S->kept[r0], k1 = S->kept[r0 + 8];
        float s0 = S->s[k0],  s1 = S->s[k1];
        int myRow = S->kept[rg * 16 + (t8 & 1) * 8 + lane7];
        uint32_t aA = smem_u32(&S->u.c1.As1[myRow][aColO]);
        uint32_t aB = smem_u32(&S->u.c1.W1s[hf * 64 + bRowO][bColO]);
        float acc[8][4];
#pragma unroll
        for (int nt = 0; nt < 8; nt++)
#pragma unroll
            for (int i = 0; i < 4; i++) acc[nt][i] = 0.0f;
#pragma unroll
        for (int ks = 0; ks < 24; ks += 8) {
            uint32_t am[4];
            ldsm4(am, aA + ks * 4);
#pragma unroll
            for (int p = 0; p < 4; p++) {
                uint32_t bp[4];
                ldsm4(bp, aB + p * 16 * 28 * 4 + ks * 4);
                mma_tf32(acc[2*p],   am[0], am[1], am[2], am[3], bp[0], bp[1]);
                mma_tf32(acc[2*p+1], am[0], am[1], am[2], am[3], bp[2], bp[3]);
            }
        }
#pragma unroll
        for (int nt = 0; nt < 8; nt++) {
            int col = hf * 64 + nt * 8 + 2 * (lane & 3);
            float v00 = fmaxf(acc[nt][0] + S->bb[col],     0.0f) * s0;
            float v01 = fmaxf(acc[nt][1] + S->bb[col + 1], 0.0f) * s0;
            float v10 = fmaxf(acc[nt][2] + S->bb[col],     0.0f) * s1;
            float v11 = fmaxf(acc[nt][3] + S->bb[col + 1], 0.0f) * s1;
            *(float2*)&S->xs[r0][col]     = make_float2(v00, v01);
            *(float2*)&S->xs[r0 + 8][col] = make_float2(v10, v11);
        }
    }
    __syncthreads();

    pool_xs(S, K1);

    // ---------- level 2 ----------
    if (tid < 128) { S->bb[tid] = b2[tid]; S->ps[tid] = p2[tid]; }
    stage_chunk(S, 0, w2n, w2r, 0);      // prefetch chunk 0 under agg
    level_agg2(S, K1, S->c2o[0]);
    level_gemm_topk(S, K1, K2, S->rns[1], w2n, w2r);

    // compose maps with topk2 result (newloc/kept in K1-current space)
    for (int i = tid; i < NP + K2; i += NT) {
        if (i < K2) {
            S->c2o[1][i] = S->c2o[0][S->kept[i]];
        } else {
            int ov = i - K2;
            short c = S->o2c[ov];
            S->o2c[ov] = (c >= 0) ? S->newloc[c] : (short)-1;
        }
    }

    // ---------- level 3 ----------
    if (tid < 128) { S->bb[tid] = b3[tid]; S->ps[tid] = p3[tid]; }
    stage_chunk(S, 0, w3n, w3r, 0);
    level_agg2(S, K2, S->c2o[1]);        // leading sync covers compose writes
    level_gemm_topk(S, K2, K3, S->rns[2], w3n, w3r);

    __syncthreads();                     // harr visibility for the MLP head

    // ---------- MLP head (coalesced warp-cooperative, float4) ----------
    {
        float4 h0 = *(const float4*)&S->harr[lane * 4];
        float4 h1v = *(const float4*)&S->harr[128 + lane * 4];
        for (int c = w; c < 128; c += NW) {
            const float4* w4 = (const float4*)(lw1 + c * 256);
            float4 w0 = w4[lane], w1v = w4[lane + 32];
            float a = w0.x*h0.x + w0.y*h0.y + w0.z*h0.z + w0.w*h0.w
                    + w1v.x*h1v.x + w1v.y*h1v.y + w1v.z*h1v.z + w1v.w*h1v.w;
#pragma unroll
            for (int o = 16; o; o >>= 1) a += __shfl_xor_sync(0xffffffffu, a, o);
            if (lane == 0) S->h1[c] = fmaxf(a + lb1[c], 0.0f);
        }
    }
    __syncthreads();
    {
        float4 g0 = *(const float4*)&S->h1[lane * 4];
        for (int c = w; c < 64; c += NW) {
            float4 w0 = ((const float4*)(lw2 + c * 128))[lane];
            float a = w0.x*g0.x + w0.y*g0.y + w0.z*g0.z + w0.w*g0.w;
#pragma unroll
            for (int o = 16; o; o >>= 1) a += __shfl_xor_sync(0xffffffffu, a, o);
            if (lane == 0) S->h2[c] = fmaxf(a + lb2[c], 0.0f);
        }
    }
    __syncthreads();
    if (w == 0) {
        float a = 0.0f;
#pragma unroll
        for (int j = 0; j < 2; j++)
            a += lw3[j*32 + lane] * S->h2[j*32 + lane];
#pragma unroll
        for (int o = 16; o; o >>= 1) a += __shfl_xor_sync(0xffffffffu, a, o);
        if (lane == 0) out[b] = 1.0f / (1.0f + expf(-(a + lb3[0])));
    }
}

// ---------------- launch ------------------------------------------------------
extern "C" void kernel_launch(void* const* d_in, const int* in_sizes, int n_in,
                              void* d_out, int out_size) {
    const int*   node_ids   = (const int*)d_in[0];
    const int*   edge_index = (const int*)d_in[1];
    const float* emb  = (const float*)d_in[3];
    const float* w1n  = (const float*)d_in[4];
    const float* w1r  = (const float*)d_in[5];
    const float* b1   = (const float*)d_in[6];
    const float* w2n  = (const float*)d_in[7];
    const float* w2r  = (const float*)d_in[8];
    const float* b2   = (const float*)d_in[9];
    const float* w3n  = (const float*)d_in[10];
    const float* w3r  = (const float*)d_in[11];
    const float* b3   = (const float*)d_in[12];
    const float* p1   = (const float*)d_in[13];
    const float* p2   = (const float*)d_in[14];
    const float* p3   = (const float*)d_in[15];
    const float* lw1  = (const float*)d_in[16];
    const float* lb1  = (const float*)d_in[17];
    const float* lw2  = (const float*)d_in[18];
    const float* lb2  = (const float*)d_in[19];
    const float* lw3  = (const float*)d_in[20];
    const float* lb3  = (const float*)d_in[21];
    float* out = (float*)d_out;

    static int smem_set = 0;
    if (!smem_set) {
        cudaFuncSetAttribute(mega_kernel,
                             cudaFuncAttributeMaxDynamicSharedMemorySize,
                             (int)sizeof(MegaSm));
        smem_set = 1;
    }

    mega_kernel<<<B, NT, sizeof(MegaSm)>>>(
        node_ids, edge_index, emb,
        w1n, w1r, b1, p1,
        w2n, w2r, b2, p2,
        w3n, w3r, b3, p3,
        lw1, lb1, lw2, lb2, lw3, lb3, out);
}

// round 17
// speedup vs baseline: 1.0307x; 1.0307x over previous
#include <cuda_runtime.h>
#include <math.h>
#include <stdint.h>

#define B    512
#define NP   200
#define EPG  2000
#define E_TOT (B*EPG)
#define HID  128
#define EMB  9
#define K1   160
#define K2   128
#define K3   103

#define NT   768           // threads
#define NW   24            // warps
#define INV_E 0xFFu
#define XSTR 132           // xs/ms row stride (floats)

// ---------------- async copy helpers -----------------------------------------
__device__ __forceinline__ void cp_async16(void* smem_dst, const void* gsrc) {
    uint32_t s = (uint32_t)__cvta_generic_to_shared(smem_dst);
    asm volatile("cp.async.ca.shared.global [%0], [%1], 16;\n" :: "r"(s), "l"(gsrc));
}
__device__ __forceinline__ void cp_commit() {
    asm volatile("cp.async.commit_group;\n" ::: "memory");
}
template<int N>
__device__ __forceinline__ void cp_wait() {
    asm volatile("cp.async.wait_group %0;\n" :: "n"(N) : "memory");
}

// ---------------- tf32 mma + ldmatrix primitives ------------------------------
__device__ __forceinline__ void mma_tf32(float c[4], uint32_t a0, uint32_t a1,
                                         uint32_t a2, uint32_t a3,
                                         uint32_t b0, uint32_t b1) {
    asm volatile(
        "mma.sync.aligned.m16n8k8.row.col.f32.tf32.tf32.f32 "
        "{%0,%1,%2,%3}, {%4,%5,%6,%7}, {%8,%9}, {%0,%1,%2,%3};"
        : "+f"(c[0]), "+f"(c[1]), "+f"(c[2]), "+f"(c[3])
        : "r"(a0), "r"(a1), "r"(a2), "r"(a3), "r"(b0), "r"(b1));
}
__device__ __forceinline__ void ldsm4(uint32_t r[4], uint32_t addr) {
    asm volatile("ldmatrix.sync.aligned.m8n8.x4.shared.b16 {%0,%1,%2,%3}, [%4];"
        : "=r"(r[0]), "=r"(r[1]), "=r"(r[2]), "=r"(r[3]) : "r"(addr));
}
__device__ __forceinline__ uint32_t smem_u32(const void* p) {
    return (uint32_t)__cvta_generic_to_shared(p);
}

// ---------------- mega kernel smem -------------------------------------------
struct MegaSm {
    float xs[160][XSTR];     // pooled features (current space)
    float ms[160][XSTR];     // neighbor means (current space)
    union {
        struct {             // conv1 phase
            float As1[208][28];   // [mean(9) | x(9) | pad] per node
            float W1s[128][28];   // [w1n | w1r | pad]
        } c1;
        float wst2[2][128][36];  // level-GEMM W k-chunk double buffer
    } u;
    float s[208];            // scores (n is always a multiple of 4)
    float sdp[4][208];       // deterministic 4-part score dot (conv1 uses 2)
    float bb[128];
    float ps[128];
    float harr[256];         // readout accumulator x1+x2+x3
    float pmax[6][128];
    float psum[6][128];
    float h1[128];
    float h2[64];
    float rns[3];
    int   hist[224];
    int   off[225];          // ORIGINAL-space CSR offsets (built once)
    int   cur[224];
    int   wsum[8];
    short newloc[208];
    short kept[160];
    short c2o[2][160];       // current -> orig per level (0: after topk1)
    unsigned char esrc[EPG];
    unsigned char edst[EPG];
    unsigned char eord[EPG]; // srcs sorted by ORIGINAL dst; REBASED into the
                             // current index space after each topk (0xFF dead)
};

// parallel exclusive scan of hist[0..n) -> off/cur, off[n]=total
__device__ __forceinline__ void excl_scan(MegaSm* S, int n) {
    int tid = threadIdx.x, lane = tid & 31, w = tid >> 5;
    int npad = (n + 31) & ~31;
    if (tid < npad) {
        int h0 = S->hist[tid];
        int x = h0;
#pragma unroll
        for (int o = 1; o < 32; o <<= 1) {
            int y = __shfl_up_sync(0xffffffffu, x, o);
            if (lane >= o) x += y;
        }
        if (lane == 31) S->wsum[w] = x;
        S->off[tid] = x - h0;
    }
    __syncthreads();
    if (tid == 0) {
        int a = 0, nw = npad >> 5;
        for (int i = 0; i < nw; i++) { int t = S->wsum[i]; S->wsum[i] = a; a += t; }
        S->off[n] = a;
    }
    __syncthreads();
    if (tid < n) {
        int o = S->off[tid] + S->wsum[w];
        S->off[tid] = o;
        S->cur[tid] = o;
    }
    __syncthreads();
}

// one-time counting sort of edges by ORIGINAL dst into eord
__device__ __forceinline__ void edge_sort_once(MegaSm* S) {
    int tid = threadIdx.x;
    for (int i = tid; i < 224; i += NT) S->hist[i] = 0;
    __syncthreads();
    for (int e = tid; e < EPG; e += NT)
        atomicAdd(&S->hist[S->edst[e]], 1);
    __syncthreads();
    excl_scan(S, NP);
    for (int e = tid; e < EPG; e += NT) {
        int p = atomicAdd(&S->cur[S->edst[e]], 1);
        S->eord[p] = S->esrc[e];
    }
    __syncthreads();
}

// 128-dim neighbor mean at levels 2/3: eord is already in the CURRENT index
// space (0xFF = dead source), so the gather chain is eord -> xs directly.
__device__ __forceinline__ void level_agg2(MegaSm* S, int n, const short* c2o) {
    __syncthreads();     // eord/c2o/xs visibility
    int tid = threadIdx.x, w = tid >> 5, lane = tid & 31;
    for (int v = w; v < n; v += NW) {
        int ov = c2o[v];
        int e0 = S->off[ov], e1 = S->off[ov + 1];
        float4 a = make_float4(0.f, 0.f, 0.f, 0.f);
        int cnt = 0;
        for (int e = e0; e < e1; e++) {
            unsigned char cs = S->eord[e];
            if (cs != INV_E) {
                float4 p = *(const float4*)&S->xs[cs][4*lane];
                a.x += p.x; a.y += p.y; a.z += p.z; a.w += p.w;
                cnt++;
            }
        }
        float inv = (cnt > 0) ? 1.0f / (float)cnt : 0.0f;
        *(float4*)&S->ms[v][4*lane] =
            make_float4(a.x * inv, a.y * inv, a.z * inv, a.w * inv);
    }
    __syncthreads();
}

// 3-way split rank with float4 inner loads; hist pre-zeroed by caller.
__device__ __forceinline__ void level_rank(MegaSm* S, int n, int k) {
    int tid = threadIdx.x;
    int v = tid & 255;
    int part = tid >> 8;                 // 0..2 (768 = 3*256)
    if (v < n) {
        int chunk = (((n + 2) / 3) + 3) & ~3;
        int u0 = part * chunk;
        int u1 = min(n, u0 + chunk);
        float sv = S->s[v];
        int r = 0;
        int u = u0;
        for (; u + 4 <= u1; u += 4) {
            float4 s4 = *(const float4*)&S->s[u];
            r += (s4.x > sv) || (s4.x == sv && (u + 0) < v);
            r += (s4.y > sv) || (s4.y == sv && (u + 1) < v);
            r += (s4.z > sv) || (s4.z == sv && (u + 2) < v);
            r += (s4.w > sv) || (s4.w == sv && (u + 3) < v);
        }
        for (; u < u1; u++) {
            float su = S->s[u];
            r += (su > sv) || (su == sv && u < v);
        }
        atomicAdd(&S->hist[v], r);
    }
    __syncthreads();
    for (int v2 = tid; v2 < n; v2 += NT) {
        int r = S->hist[v2];
        S->newloc[v2] = (r < k) ? (short)r : (short)-1;
        if (r < k) S->kept[r] = (short)v2;
    }
    __syncthreads();
}

// pool xs rows [0,k) into harr (6 row-slices). No trailing sync (audited).
__device__ __forceinline__ void pool_xs(MegaSm* S, int k) {
    int tid = threadIdx.x;
    int d = tid & 127, sl = tid >> 7;    // 0..5
    float mx = -INFINITY, sm = 0.0f;
    for (int r = sl; r < k; r += 6) {
        float v = S->xs[r][d];
        mx = fmaxf(mx, v);
        sm += v;
    }
    S->pmax[sl][d] = mx;
    S->psum[sl][d] = sm;
    __syncthreads();
    if (tid < 128) {
        float m = S->pmax[0][tid];
        float t = S->psum[0][tid];
#pragma unroll
        for (int i = 1; i < 6; i++) {
            m = fmaxf(m, S->pmax[i][tid]);
            t += S->psum[i][tid];
        }
        S->harr[tid]       += m;
        S->harr[128 + tid] += t / (float)k;
    }
}

// stage one 32-k chunk of the level weights into wst2[buf]
__device__ __forceinline__ void stage_chunk(
        MegaSm* S, int buf, const float* __restrict__ Wn,
        const float* __restrict__ Wr, int ci) {
    const float* Wg = (ci < 4) ? Wn : Wr;
    int kg = (ci * 32) & 127;
    int tid = threadIdx.x;
    for (int idx = tid; idx < 1024; idx += NT) {
        int r = idx >> 3, q = idx & 7;
        cp_async16(&S->u.wst2[buf][r][q * 4], &Wg[r * 128 + kg + q * 4]);
    }
    cp_commit();
}

// level GEMM, single sync per k-chunk, LDSM fragment loads.
// Fused score+topk+scatter+pool; optional eord rebase into the new space.
__device__ __forceinline__ void level_gemm_topk(
        MegaSm* S, int n, int k, float rn,
        const float* __restrict__ Wn, const float* __restrict__ Wr,
        bool rewrite_eord) {
    int tid = threadIdx.x, lane = tid & 31, w = tid >> 5;
    int rg = w >> 2, cf = w & 3;
    bool active = (rg < (n >> 5));

    // ldmatrix lane roles
    int t8    = lane >> 3;                       // tile index 0..3
    int lane7 = lane & 7;
    int aRow  = rg * 32 + (t8 & 1) * 8 + lane7;  // A: tiles 0/2 rows, 1/3 rows+8
    int aColO = (t8 >> 1) * 4;                   // A: tiles 2,3 at col+4
    int bRow  = cf * 32 + (t8 >> 1) * 8 + lane7; // B: tile pair rows
    int bColO = (t8 & 1) * 4;                    // B: tiles 1,3 at col+4

    float acc[2][4][4];
#pragma unroll
    for (int mt = 0; mt < 2; mt++)
#pragma unroll
        for (int nt = 0; nt < 4; nt++)
#pragma unroll
            for (int i = 0; i < 4; i++) acc[mt][nt][i] = 0.0f;

#pragma unroll 1
    for (int ci = 0; ci < 8; ci++) {
        cp_wait<0>();
        __syncthreads();   // chunk ci visible; all warps done with buf (ci+1)&1
        if (ci < 7) stage_chunk(S, (ci + 1) & 1, Wn, Wr, ci + 1);

        int nb = ci & 1;
        if (active) {
            int kc = ci * 32;
            const float (*A)[XSTR] = (kc < 128) ? S->ms : S->xs;
            int kg = kc & 127;
            uint32_t aA = smem_u32(&A[aRow][kg + aColO]);
            uint32_t aB = smem_u32(&S->u.wst2[nb][bRow][bColO]);
#pragma unroll
            for (int ks = 0; ks < 32; ks += 8) {
                uint32_t am0[4], am1[4], bp0[4], bp1[4];
                ldsm4(am0, aA + ks * 4);
                ldsm4(am1, aA + 16 * XSTR * 4 + ks * 4);
                ldsm4(bp0, aB + ks * 4);
                ldsm4(bp1, aB + 16 * 36 * 4 + ks * 4);
                mma_tf32(acc[0][0], am0[0], am0[1], am0[2], am0[3], bp0[0], bp0[1]);
                mma_tf32(acc[0][1], am0[0], am0[1], am0[2], am0[3], bp0[2], bp0[3]);
                mma_tf32(acc[0][2], am0[0], am0[1], am0[2], am0[3], bp1[0], bp1[1]);
                mma_tf32(acc[0][3], am0[0], am0[1], am0[2], am0[3], bp1[2], bp1[3]);
                mma_tf32(acc[1][0], am1[0], am1[1], am1[2], am1[3], bp0[0], bp0[1]);
                mma_tf32(acc[1][1], am1[0], am1[1], am1[2], am1[3], bp0[2], bp0[3]);
                mma_tf32(acc[1][2], am1[0], am1[1], am1[2], am1[3], bp1[0], bp1[1]);
                mma_tf32(acc[1][3], am1[0], am1[1], am1[2], am1[3], bp1[2], bp1[3]);
            }
        }
    }

    if (active) {
#pragma unroll
        for (int mt = 0; mt < 2; mt++) {
            int r = rg * 32 + mt * 16 + (lane >> 2);
            float pd0 = 0.0f, pd1 = 0.0f;
#pragma unroll
            for (int nt = 0; nt < 4; nt++) {
                int col = cf * 32 + nt * 8 + 2 * (lane & 3);
                float v00 = fmaxf(acc[mt][nt][0] + S->bb[col],     0.0f);
                float v01 = fmaxf(acc[mt][nt][1] + S->bb[col + 1], 0.0f);
                float v10 = fmaxf(acc[mt][nt][2] + S->bb[col],     0.0f);
                float v11 = fmaxf(acc[mt][nt][3] + S->bb[col + 1], 0.0f);
                acc[mt][nt][0] = v00; acc[mt][nt][1] = v01;
                acc[mt][nt][2] = v10; acc[mt][nt][3] = v11;
                pd0 += v00 * S->ps[col] + v01 * S->ps[col + 1];
                pd1 += v10 * S->ps[col] + v11 * S->ps[col + 1];
            }
            pd0 += __shfl_xor_sync(0xffffffffu, pd0, 1);
            pd0 += __shfl_xor_sync(0xffffffffu, pd0, 2);
            pd1 += __shfl_xor_sync(0xffffffffu, pd1, 1);
            pd1 += __shfl_xor_sync(0xffffffffu, pd1, 2);
            if ((lane & 3) == 0) { S->sdp[cf][r] = pd0; S->sdp[cf][r + 8] = pd1; }
        }
    }
    __syncthreads();

    // score write + rank-hist zeroing in one synced phase
    for (int v = tid; v < n; v += NT) {
        S->s[v] = tanhf(((S->sdp[0][v] + S->sdp[1][v]) +
                         (S->sdp[2][v] + S->sdp[3][v])) * rn);
        S->hist[v] = 0;
    }
    __syncthreads();

    level_rank(S, n, k);

    if (active) {
#pragma unroll
        for (int mt = 0; mt < 2; mt++) {
            int r = rg * 32 + mt * 16 + (lane >> 2);
            int nl0 = S->newloc[r], nl1 = S->newloc[r + 8];
            float s0 = S->s[r], s1 = S->s[r + 8];
#pragma unroll
            for (int nt = 0; nt < 4; nt++) {
                int col = cf * 32 + nt * 8 + 2 * (lane & 3);
                if (nl0 >= 0)
                    *(float2*)&S->xs[nl0][col] =
                        make_float2(acc[mt][nt][0] * s0, acc[mt][nt][1] * s0);
                if (nl1 >= 0)
                    *(float2*)&S->xs[nl1][col] =
                        make_float2(acc[mt][nt][2] * s1, acc[mt][nt][3] * s1);
            }
        }
    }
    // eord rebase into the new index space (rides in the scatter phase)
    if (rewrite_eord) {
        for (int e = tid; e < EPG; e += NT) {
            unsigned char v = S->eord[e];
            if (v != INV_E) {
                short nl = S->newloc[v];
                S->eord[e] = (nl >= 0) ? (unsigned char)nl : (unsigned char)INV_E;
            }
        }
    }
    __syncthreads();

    pool_xs(S, k);
}

// ---------------- the single fused kernel ------------------------------------
__global__ __launch_bounds__(NT, 1) void mega_kernel(
        const int* __restrict__ node_ids,
        const int* __restrict__ edge_index,
        const float* __restrict__ emb,
        const float* __restrict__ w1n, const float* __restrict__ w1r,
        const float* __restrict__ b1,  const float* __restrict__ p1,
        const float* __restrict__ w2n, const float* __restrict__ w2r,
        const float* __restrict__ b2,  const float* __restrict__ p2,
        const float* __restrict__ w3n, const float* __restrict__ w3r,
        const float* __restrict__ b3,  const float* __restrict__ p3,
        const float* __restrict__ lw1, const float* __restrict__ lb1,
        const float* __restrict__ lw2, const float* __restrict__ lb2,
        const float* __restrict__ lw3, const float* __restrict__ lb3,
        float* __restrict__ out) {
    extern __shared__ char raw[];
    MegaSm* S = (MegaSm*)raw;

    int b = blockIdx.x, tid = threadIdx.x;
    int w = tid >> 5, lane = tid & 31;

    // edges -> smem (uint8 original indices)
    for (int e = tid; e < EPG; e += NT) {
        S->esrc[e] = (unsigned char)(edge_index[b*EPG + e] - b*NP);
        S->edst[e] = (unsigned char)(edge_index[E_TOT + b*EPG + e] - b*NP);
    }
    // 1/||p|| for the three pool vectors
    if (w < 3) {
        const float* pv = (w == 0) ? p1 : ((w == 1) ? p2 : p3);
        float v = pv[lane]*pv[lane] + pv[lane+32]*pv[lane+32]
                + pv[lane+64]*pv[lane+64] + pv[lane+96]*pv[lane+96];
#pragma unroll
        for (int o = 16; o; o >>= 1) v += __shfl_down_sync(0xffffffffu, v, o);
        if (lane == 0) S->rns[w] = 1.0f / sqrtf(v);
    }
    if (tid < 256) S->harr[tid] = 0.0f;
    if (tid < 128) { S->bb[tid] = b1[tid]; S->ps[tid] = p1[tid]; }

    // As1: zero everything; fill emb features into cols 9..17 for v<200
    for (int idx = tid; idx < 208*28; idx += NT) {
        int r = idx / 28, c = idx - r*28;
        float v = 0.0f;
        if (r < NP && c >= 9 && c < 18)
            v = emb[(size_t)node_ids[b*NP + r] * EMB + (c - 9)];
        S->u.c1.As1[r][c] = v;
    }
    // W1 stage [w1n | w1r | pad]
    for (int idx = tid; idx < 128*28; idx += NT) {
        int r = idx / 28, c = idx - r*28;
        float wv = 0.0f;
        if (c < 9)       wv = w1n[r*9 + c];
        else if (c < 18) wv = w1r[r*9 + (c - 9)];
        S->u.c1.W1s[r][c] = wv;
    }
    __syncthreads();

    // ---------- one-time edge sort + level-1 9-dim aggregation ----------
    edge_sort_once(S);
    for (int v = w; v < NP; v += NW) {
        int e0 = S->off[v], e1 = S->off[v+1];
        float inv = (e1 > e0) ? 1.0f / (float)(e1 - e0) : 0.0f;
        if (lane < EMB) {
            float a = 0.0f;
            for (int e = e0; e < e1; e++)
                a += S->u.c1.As1[S->eord[e]][9 + lane];
            S->u.c1.As1[v][lane] = a * inv;
        }
    }
    __syncthreads();

    // ---------- conv1 pass 1: score dot only (26 tasks, K=24, LDSM) ----------
    {
        int t8    = lane >> 3;
        int lane7 = lane & 7;
        int aRowO = (t8 & 1) * 8 + lane7;
        int aColO = (t8 >> 1) * 4;
        int bRowO = (t8 >> 1) * 8 + lane7;
        int bColO = (t8 & 1) * 4;
#pragma unroll
        for (int ti = 0; ti < 2; ti++) {
            int t = w + ti * NW;
            if (t < 26) {
                int rg = t >> 1, hf = t & 1;
                float acc[8][4];
#pragma unroll
                for (int nt = 0; nt < 8; nt++)
#pragma unroll
                    for (int i = 0; i < 4; i++) acc[nt][i] = 0.0f;
                uint32_t aA = smem_u32(&S->u.c1.As1[rg * 16 + aRowO][aColO]);
                uint32_t aB = smem_u32(&S->u.c1.W1s[hf * 64 + bRowO][bColO]);
#pragma unroll
                for (int ks = 0; ks < 24; ks += 8) {
                    uint32_t am[4];
                    ldsm4(am, aA + ks * 4);
#pragma unroll
                    for (int p = 0; p < 4; p++) {
                        uint32_t bp[4];
                        ldsm4(bp, aB + p * 16 * 28 * 4 + ks * 4);
                        mma_tf32(acc[2*p],   am[0], am[1], am[2], am[3], bp[0], bp[1]);
                        mma_tf32(acc[2*p+1], am[0], am[1], am[2], am[3], bp[2], bp[3]);
                    }
                }
                int r = rg * 16 + (lane >> 2);
                float pd0 = 0.0f, pd1 = 0.0f;
#pragma unroll
                for (int nt = 0; nt < 8; nt++) {
                    int col = hf * 64 + nt * 8 + 2 * (lane & 3);
                    pd0 += fmaxf(acc[nt][0] + S->bb[col],     0.0f) * S->ps[col]
                         + fmaxf(acc[nt][1] + S->bb[col + 1], 0.0f) * S->ps[col + 1];
                    pd1 += fmaxf(acc[nt][2] + S->bb[col],     0.0f) * S->ps[col]
                         + fmaxf(acc[nt][3] + S->bb[col + 1], 0.0f) * S->ps[col + 1];
                }
                pd0 += __shfl_xor_sync(0xffffffffu, pd0, 1);
                pd0 += __shfl_xor_sync(0xffffffffu, pd0, 2);
                pd1 += __shfl_xor_sync(0xffffffffu, pd1, 1);
                pd1 += __shfl_xor_sync(0xffffffffu, pd1, 2);
                if ((lane & 3) == 0) { S->sdp[hf][r] = pd0; S->sdp[hf][r + 8] = pd1; }
            }
        }
    }
    __syncthreads();

    for (int v = tid; v < NP; v += NT) {
        S->s[v] = tanhf((S->sdp[0][v] + S->sdp[1][v]) * S->rns[0]);
        S->hist[v] = 0;
    }
    __syncthreads();

    level_rank(S, NP, K1);

    // c2o init + eord rebase orig->K1 (rides in the pass-2 phase)
    for (int r = tid; r < K1; r += NT) S->c2o[0][r] = S->kept[r];
    for (int e = tid; e < EPG; e += NT) {
        short nl = S->newloc[S->eord[e]];
        S->eord[e] = (nl >= 0) ? (unsigned char)nl : (unsigned char)INV_E;
    }

    // ---------- conv1 pass 2: recompute kept rows, gain, write xs ----------
    if (w < 20) {
        int rg = w >> 1, hf = w & 1;
        int r0 = rg * 16 + (lane >> 2);
        int k0 = S->kept[r0], k1 = S->kept[r0 + 8];
        float s0 = S->s[k0],  s1 = S->s[k1];
        float acc[8][4];
#pragma unroll
        for (int nt = 0; nt < 8; nt++)
#pragma unroll
            for (int i = 0; i < 4; i++) acc[nt][i] = 0.0f;
#pragma unroll
        for (int ks = 0; ks < 24; ks += 8) {
            int c = ks + (lane & 3);
            uint32_t a0 = __float_as_uint(S->u.c1.As1[k0][c]);
            uint32_t a1 = __float_as_uint(S->u.c1.As1[k1][c]);
            uint32_t a2 = __float_as_uint(S->u.c1.As1[k0][c + 4]);
            uint32_t a3 = __float_as_uint(S->u.c1.As1[k1][c + 4]);
#pragma unroll
            for (int nt = 0; nt < 8; nt++) {
                int nr = hf * 64 + nt * 8 + (lane >> 2);
                uint32_t b0 = __float_as_uint(S->u.c1.W1s[nr][c]);
                uint32_t b1 = __float_as_uint(S->u.c1.W1s[nr][c + 4]);
                mma_tf32(acc[nt], a0, a1, a2, a3, b0, b1);
            }
        }
#pragma unroll
        for (int nt = 0; nt < 8; nt++) {
            int col = hf * 64 + nt * 8 + 2 * (lane & 3);
            float v00 = fmaxf(acc[nt][0] + S->bb[col],     0.0f) * s0;
            float v01 = fmaxf(acc[nt][1] + S->bb[col + 1], 0.0f) * s0;
            float v10 = fmaxf(acc[nt][2] + S->bb[col],     0.0f) * s1;
            float v11 = fmaxf(acc[nt][3] + S->bb[col + 1], 0.0f) * s1;
            *(float2*)&S->xs[r0][col]     = make_float2(v00, v01);
            *(float2*)&S->xs[r0 + 8][col] = make_float2(v10, v11);
        }
    }
    __syncthreads();

    pool_xs(S, K1);

    // ---------- level 2 ----------
    if (tid < 128) { S->bb[tid] = b2[tid]; S->ps[tid] = p2[tid]; }
    stage_chunk(S, 0, w2n, w2r, 0);      // prefetch chunk 0 under agg
    level_agg2(S, K1, S->c2o[0]);
    level_gemm_topk(S, K1, K2, S->rns[1], w2n, w2r, true);

    // compose c2o with topk2 result (kept in K1-current space)
    for (int r = tid; r < K2; r += NT) S->c2o[1][r] = S->c2o[0][S->kept[r]];

    // ---------- level 3 ----------
    if (tid < 128) { S->bb[tid] = b3[tid]; S->ps[tid] = p3[tid]; }
    stage_chunk(S, 0, w3n, w3r, 0);
    level_agg2(S, K2, S->c2o[1]);        // leading sync covers compose writes
    level_gemm_topk(S, K2, K3, S->rns[2], w3n, w3r, false);

    __syncthreads();                     // harr visibility for the MLP head

    // ---------- MLP head (coalesced warp-cooperative, float4) ----------
    {
        float4 h0 = *(const float4*)&S->harr[lane * 4];
        float4 h1v = *(const float4*)&S->harr[128 + lane * 4];
        for (int c = w; c < 128; c += NW) {
            const float4* w4 = (const float4*)(lw1 + c * 256);
            float4 w0 = w4[lane], w1v = w4[lane + 32];
            float a = w0.x*h0.x + w0.y*h0.y + w0.z*h0.z + w0.w*h0.w
                    + w1v.x*h1v.x + w1v.y*h1v.y + w1v.z*h1v.z + w1v.w*h1v.w;
#pragma unroll
            for (int o = 16; o; o >>= 1) a += __shfl_xor_sync(0xffffffffu, a, o);
            if (lane == 0) S->h1[c] = fmaxf(a + lb1[c], 0.0f);
        }
    }
    __syncthreads();
    {
        float4 g0 = *(const float4*)&S->h1[lane * 4];
        for (int c = w; c < 64; c += NW) {
            float4 w0 = ((const float4*)(lw2 + c * 128))[lane];
            float a = w0.x*g0.x + w0.y*g0.y + w0.z*g0.z + w0.w*g0.w;
#pragma unroll
            for (int o = 16; o; o >>= 1) a += __shfl_xor_sync(0xffffffffu, a, o);
            if (lane == 0) S->h2[c] = fmaxf(a + lb2[c], 0.0f);
        }
    }
    __syncthreads();
    if (w == 0) {
        float a = 0.0f;
#pragma unroll
        for (int j = 0; j < 2; j++)
            a += lw3[j*32 + lane] * S->h2[j*32 + lane];
#pragma unroll
        for (int o = 16; o; o >>= 1) a += __shfl_xor_sync(0xffffffffu, a, o);
        if (lane == 0) out[b] = 1.0f / (1.0f + expf(-(a + lb3[0])));
    }
}

// ---------------- launch ------------------------------------------------------
extern "C" void kernel_launch(void* const* d_in, const int* in_sizes, int n_in,
                              void* d_out, int out_size) {
    const int*   node_ids   = (const int*)d_in[0];
    const int*   edge_index = (const int*)d_in[1];
    const float* emb  = (const float*)d_in[3];
    const float* w1n  = (const float*)d_in[4];
    const float* w1r  = (const float*)d_in[5];
    const float* b1   = (const float*)d_in[6];
    const float* w2n  = (const float*)d_in[7];
    const float* w2r  = (const float*)d_in[8];
    const float* b2   = (const float*)d_in[9];
    const float* w3n  = (const float*)d_in[10];
    const float* w3r  = (const float*)d_in[11];
    const float* b3   = (const float*)d_in[12];
    const float* p1   = (const float*)d_in[13];
    const float* p2   = (const float*)d_in[14];
    const float* p3   = (const float*)d_in[15];
    const float* lw1  = (const float*)d_in[16];
    const float* lb1  = (const float*)d_in[17];
    const float* lw2  = (const float*)d_in[18];
    const float* lb2  = (const float*)d_in[19];
    const float* lw3  = (const float*)d_in[20];
    const float* lb3  = (const float*)d_in[21];
    float* out = (float*)d_out;

    static int smem_set = 0;
    if (!smem_set) {
        cudaFuncSetAttribute(mega_kernel,
                             cudaFuncAttributeMaxDynamicSharedMemorySize,
                             (int)sizeof(MegaSm));
        smem_set = 1;
    }

    mega_kernel<<<B, NT, sizeof(MegaSm)>>>(
        node_ids, edge_index, emb,
        w1n, w1r, b1, p1,
        w2n, w2r, b2, p2,
        w3n, w3r, b3, p3,
        lw1, lb1, lw2, lb2, lw3, lb3, out);
}